// round 1
// baseline (speedup 1.0000x reference)
#include <cuda_runtime.h>

// Problem constants
#define B_ 4
#define T_ 2048
#define C_ 2048
#define H_ 16
#define D_ 128

// Scratch (device globals: allocation-free per harness rules)
__device__ float g_Q[(size_t)B_ * H_ * T_ * D_];     // [B,H,T,Dh]
__device__ float g_K[(size_t)B_ * H_ * T_ * D_];
__device__ float g_V[(size_t)B_ * H_ * T_ * D_];
__device__ float g_ATT[(size_t)B_ * T_ * C_];        // [B,T,C] attention output

// ---------------------------------------------------------------------------
// Tiled fp32 GEMM:  C[M,N] = A[M,K] @ W[N,K]^T + bias[N]
// Tile 128x128, BK=16, 256 threads, 8x8 per thread.
// mode 0: QKV projection, scatter epilogue into g_Q/g_K/g_V  (N = 6144)
// mode 1: output projection into Out (row-major [M, C_])     (N = 2048)
// A_in == nullptr means "read from g_ATT".
// ---------------------------------------------------------------------------
__global__ void __launch_bounds__(256, 2)
gemm_kernel(const float* __restrict__ A_in, const float* __restrict__ W,
            const float* __restrict__ bias, float* __restrict__ Out, int mode)
{
    const int K = C_;
    __shared__ float As[16][132];   // stored transposed: As[k][m]
    __shared__ float Ws[16][132];   // Ws[k][n]

    const float* A = A_in ? A_in : g_ATT;

    int tid = threadIdx.x;
    int tx = tid & 15;
    int ty = tid >> 4;
    int bm = blockIdx.y << 7;
    int bn = blockIdx.x << 7;

    float acc[8][8];
#pragma unroll
    for (int i = 0; i < 8; i++)
#pragma unroll
        for (int j = 0; j < 8; j++) acc[i][j] = 0.f;

    for (int kt = 0; kt < K; kt += 16) {
#pragma unroll
        for (int s = 0; s < 2; s++) {
            int f = tid + (s << 8);          // 0..511
            int row = f >> 2;                // 0..127
            int kc = (f & 3) << 2;           // 0,4,8,12
            float4 av = *(const float4*)(A + (size_t)(bm + row) * K + kt + kc);
            As[kc + 0][row] = av.x;
            As[kc + 1][row] = av.y;
            As[kc + 2][row] = av.z;
            As[kc + 3][row] = av.w;
            float4 wv = *(const float4*)(W + (size_t)(bn + row) * K + kt + kc);
            Ws[kc + 0][row] = wv.x;
            Ws[kc + 1][row] = wv.y;
            Ws[kc + 2][row] = wv.z;
            Ws[kc + 3][row] = wv.w;
        }
        __syncthreads();

#pragma unroll
        for (int k = 0; k < 16; k++) {
            float a[8], b[8];
            *(float4*)(a)     = *(const float4*)(&As[k][(ty << 3)]);
            *(float4*)(a + 4) = *(const float4*)(&As[k][(ty << 3) + 4]);
            *(float4*)(b)     = *(const float4*)(&Ws[k][(tx << 3)]);
            *(float4*)(b + 4) = *(const float4*)(&Ws[k][(tx << 3) + 4]);
#pragma unroll
            for (int i = 0; i < 8; i++)
#pragma unroll
                for (int j = 0; j < 8; j++)
                    acc[i][j] = fmaf(a[i], b[j], acc[i][j]);
        }
        __syncthreads();
    }

    int col = bn + (tx << 3);
    float bb[8];
#pragma unroll
    for (int j = 0; j < 8; j++) bb[j] = bias[col + j];

    if (mode == 0) {
        // blockIdx.x spans n in [bn, bn+128) == one (sel, head) slice exactly
        int sel = blockIdx.x >> 4;          // 0:q 1:k 2:v
        int h = blockIdx.x & 15;
        float* dst = (sel == 0) ? g_Q : ((sel == 1) ? g_K : g_V);
#pragma unroll
        for (int i = 0; i < 8; i++) {
            int row = bm + (ty << 3) + i;   // 0..8191 == b*T + t
            int b = row >> 11;
            int t = row & 2047;
            size_t base = (((size_t)(b * H_ + h)) * T_ + t) * D_ + (tx << 3);
            float4 v0 = make_float4(acc[i][0] + bb[0], acc[i][1] + bb[1],
                                    acc[i][2] + bb[2], acc[i][3] + bb[3]);
            float4 v1 = make_float4(acc[i][4] + bb[4], acc[i][5] + bb[5],
                                    acc[i][6] + bb[6], acc[i][7] + bb[7]);
            *(float4*)(dst + base)     = v0;
            *(float4*)(dst + base + 4) = v1;
        }
    } else {
#pragma unroll
        for (int i = 0; i < 8; i++) {
            int row = bm + (ty << 3) + i;
            size_t base = (size_t)row * C_ + col;
            float4 v0 = make_float4(acc[i][0] + bb[0], acc[i][1] + bb[1],
                                    acc[i][2] + bb[2], acc[i][3] + bb[3]);
            float4 v1 = make_float4(acc[i][4] + bb[4], acc[i][5] + bb[5],
                                    acc[i][6] + bb[6], acc[i][7] + bb[7]);
            *(float4*)(Out + base)     = v0;
            *(float4*)(Out + base + 4) = v1;
        }
    }
}

// ---------------------------------------------------------------------------
// Flash attention (fp32, online softmax, causal block skipping).
// grid = (T/64, B*H); block = 256 threads (16x16 thread tile).
// Each CTA: 64 queries x Dh=128; loops key blocks kb = 0..qb.
// S tile 64x64: thread (ty,tx) owns 4x4.  O tile 64x128: thread owns 4x8.
// ---------------------------------------------------------------------------
#define QT_S 65     // Qt/Kt row stride (transposed [d][row])
#define VS_S 132    // Vs row stride ([row][d])
#define PS_S 65     // Ps row stride
#define SMEM_ATTN ((2 * 128 * QT_S + 64 * VS_S + 64 * PS_S) * 4)

__global__ void __launch_bounds__(256)
attn_kernel()
{
    extern __shared__ float sm[];
    float* Qt = sm;                     // [128][QT_S]  (d-major)
    float* Kt = Qt + 128 * QT_S;        // [128][QT_S]
    float* Vs = Kt + 128 * QT_S;        // [64][VS_S]   (row-major)
    float* Ps = Vs + 64 * VS_S;         // [64][PS_S]

    int tid = threadIdx.x;
    int tx = tid & 15;
    int ty = tid >> 4;
    int qb = blockIdx.x;
    int bh = blockIdx.y;

    const float* Qp = g_Q + (size_t)bh * T_ * D_ + (size_t)qb * 64 * D_;
    const float* Kp = g_K + (size_t)bh * T_ * D_;
    const float* Vp = g_V + (size_t)bh * T_ * D_;

    // Load Q tile transposed into Qt[d][row]
#pragma unroll
    for (int s = 0; s < 8; s++) {
        int f = tid + (s << 8);
        int row = f >> 5;                // 0..63
        int dc = (f & 31) << 2;          // 0..124
        float4 v = *(const float4*)(Qp + (size_t)row * D_ + dc);
        Qt[(dc + 0) * QT_S + row] = v.x;
        Qt[(dc + 1) * QT_S + row] = v.y;
        Qt[(dc + 2) * QT_S + row] = v.z;
        Qt[(dc + 3) * QT_S + row] = v.w;
    }

    float m_i[4], l_i[4], o[4][8];
#pragma unroll
    for (int i = 0; i < 4; i++) {
        m_i[i] = -3.0e38f;
        l_i[i] = 0.f;
#pragma unroll
        for (int j = 0; j < 8; j++) o[i][j] = 0.f;
    }

    const float scale = 0.088388347648318447f;  // 1/sqrt(128)

    for (int kb = 0; kb <= qb; kb++) {
        __syncthreads();   // previous iter done with Kt/Vs/Ps

        // Load K (transposed) and V tiles
#pragma unroll
        for (int s = 0; s < 8; s++) {
            int f = tid + (s << 8);
            int row = f >> 5;
            int dc = (f & 31) << 2;
            size_t goff = (size_t)(kb * 64 + row) * D_ + dc;
            float4 kv = *(const float4*)(Kp + goff);
            Kt[(dc + 0) * QT_S + row] = kv.x;
            Kt[(dc + 1) * QT_S + row] = kv.y;
            Kt[(dc + 2) * QT_S + row] = kv.z;
            Kt[(dc + 3) * QT_S + row] = kv.w;
            float4 vv = *(const float4*)(Vp + goff);
            *(float4*)(&Vs[row * VS_S + dc]) = vv;
        }
        __syncthreads();

        // S = Q @ K^T : 4x4 per thread over k=128
        float sacc[4][4];
#pragma unroll
        for (int i = 0; i < 4; i++)
#pragma unroll
            for (int j = 0; j < 4; j++) sacc[i][j] = 0.f;

#pragma unroll 4
        for (int kk = 0; kk < 128; kk++) {
            float a[4], bv[4];
#pragma unroll
            for (int i = 0; i < 4; i++) a[i] = Qt[kk * QT_S + (ty << 2) + i];
#pragma unroll
            for (int j = 0; j < 4; j++) bv[j] = Kt[kk * QT_S + (tx << 2) + j];
#pragma unroll
            for (int i = 0; i < 4; i++)
#pragma unroll
                for (int j = 0; j < 4; j++)
                    sacc[i][j] = fmaf(a[i], bv[j], sacc[i][j]);
        }

        bool diag = (kb == qb);
        float p[4][4];
#pragma unroll
        for (int i = 0; i < 4; i++) {
            float rmax = -3.0e38f;
#pragma unroll
            for (int j = 0; j < 4; j++) {
                float sv = sacc[i][j] * scale;
                if (diag && ((tx << 2) + j) > ((ty << 2) + i)) sv = -3.0e38f;
                sacc[i][j] = sv;
                rmax = fmaxf(rmax, sv);
            }
            // reduce over the 16 tx lanes (lanes of same ty are contiguous in warp)
#pragma unroll
            for (int off = 1; off < 16; off <<= 1)
                rmax = fmaxf(rmax, __shfl_xor_sync(0xffffffffu, rmax, off));
            float mnew = fmaxf(m_i[i], rmax);
            float alpha = __expf(m_i[i] - mnew);
            float rs = 0.f;
#pragma unroll
            for (int j = 0; j < 4; j++) {
                float pv = __expf(sacc[i][j] - mnew);
                p[i][j] = pv;
                rs += pv;
            }
#pragma unroll
            for (int off = 1; off < 16; off <<= 1)
                rs += __shfl_xor_sync(0xffffffffu, rs, off);
            l_i[i] = l_i[i] * alpha + rs;
            m_i[i] = mnew;
#pragma unroll
            for (int j = 0; j < 8; j++) o[i][j] *= alpha;
        }

        // Stage P to shared, then O += P @ V
#pragma unroll
        for (int i = 0; i < 4; i++)
#pragma unroll
            for (int j = 0; j < 4; j++)
                Ps[((ty << 2) + i) * PS_S + (tx << 2) + j] = p[i][j];
        __syncthreads();

#pragma unroll 4
        for (int kk = 0; kk < 64; kk++) {
            float a[4];
#pragma unroll
            for (int i = 0; i < 4; i++) a[i] = Ps[((ty << 2) + i) * PS_S + kk];
            float4 b0 = *(const float4*)(&Vs[kk * VS_S + (tx << 3)]);
            float4 b1 = *(const float4*)(&Vs[kk * VS_S + (tx << 3) + 4]);
            float bv[8] = {b0.x, b0.y, b0.z, b0.w, b1.x, b1.y, b1.z, b1.w};
#pragma unroll
            for (int i = 0; i < 4; i++)
#pragma unroll
                for (int j = 0; j < 8; j++)
                    o[i][j] = fmaf(a[i], bv[j], o[i][j]);
        }
    }

    // Normalize and write to g_ATT as [B, T, C] (un-transposed layout)
    int b = bh >> 4;
    int h = bh & 15;
#pragma unroll
    for (int i = 0; i < 4; i++) {
        int t = (qb << 6) + (ty << 2) + i;
        float inv = 1.f / l_i[i];
        size_t base = ((size_t)b * T_ + t) * C_ + (h << 7) + (tx << 3);
        float4 v0 = make_float4(o[i][0] * inv, o[i][1] * inv, o[i][2] * inv, o[i][3] * inv);
        float4 v1 = make_float4(o[i][4] * inv, o[i][5] * inv, o[i][6] * inv, o[i][7] * inv);
        *(float4*)(&g_ATT[base])     = v0;
        *(float4*)(&g_ATT[base + 4]) = v1;
    }
}

// ---------------------------------------------------------------------------
extern "C" void kernel_launch(void* const* d_in, const int* in_sizes, int n_in,
                              void* d_out, int out_size)
{
    const float* x      = (const float*)d_in[0];
    const float* qkv_w  = (const float*)d_in[1];
    const float* qkv_b  = (const float*)d_in[2];
    const float* proj_w = (const float*)d_in[3];
    const float* proj_b = (const float*)d_in[4];
    float* out = (float*)d_out;

    // Idempotent, non-stream host call: OK under graph capture.
    cudaFuncSetAttribute(attn_kernel, cudaFuncAttributeMaxDynamicSharedMemorySize,
                         SMEM_ATTN);

    // 1) QKV projection: [8192,2048] @ [6144,2048]^T + b, scattered into Q/K/V
    gemm_kernel<<<dim3(48, 64), 256>>>(x, qkv_w, qkv_b, nullptr, 0);

    // 2) causal flash attention -> g_ATT [B,T,C]
    attn_kernel<<<dim3(T_ / 64, B_ * H_), 256, SMEM_ATTN>>>();

    // 3) output projection: g_ATT @ proj_w^T + proj_b -> d_out
    gemm_kernel<<<dim3(16, 64), 256>>>(nullptr, proj_w, proj_b, out, 1);
}

// round 3
// speedup vs baseline: 1.7613x; 1.7613x over previous
#include <cuda_runtime.h>
#include <cstdint>

// Problem constants
#define B_ 4
#define T_ 2048
#define C_ 2048
#define H_ 16
#define D_ 128

// Scratch (device globals: allocation-free per harness rules)
__device__ float g_Q[(size_t)B_ * H_ * T_ * D_];     // [B,H,T,Dh]
__device__ float g_K[(size_t)B_ * H_ * T_ * D_];
__device__ float g_V[(size_t)B_ * H_ * T_ * D_];
__device__ float g_ATT[(size_t)B_ * T_ * C_];        // [B,T,C] attention output

// ---------------------------------------------------------------------------
// tf32 helpers (sm_80+ PTX only — safe on base sm_103 target)
// ---------------------------------------------------------------------------
__device__ __forceinline__ float rnd_tf32(float x) {
    uint32_t u;
    asm("cvt.rna.tf32.f32 %0, %1;" : "=r"(u) : "f"(x));
    return __uint_as_float(u);
}
__device__ __forceinline__ float4 rnd4(float4 v) {
    v.x = rnd_tf32(v.x); v.y = rnd_tf32(v.y);
    v.z = rnd_tf32(v.z); v.w = rnd_tf32(v.w);
    return v;
}

// D(16x8,f32) += A(16x8,tf32) * B(8x8,tf32)
__device__ __forceinline__ void mma16n8k8(float c[4], const uint32_t a[4],
                                          const uint32_t b[2]) {
    asm volatile(
        "mma.sync.aligned.m16n8k8.row.col.f32.tf32.tf32.f32 "
        "{%0,%1,%2,%3}, {%4,%5,%6,%7}, {%8,%9}, {%0,%1,%2,%3};"
        : "+f"(c[0]), "+f"(c[1]), "+f"(c[2]), "+f"(c[3])
        : "r"(a[0]), "r"(a[1]), "r"(a[2]), "r"(a[3]), "r"(b[0]), "r"(b[1]));
}

// ===========================================================================
// Tensor-core tf32 GEMM: C[M,N] = A[M,2048] @ W[N,2048]^T + bias[N]
// CTA tile 128x128, BK=32, 256 threads (8 warps, 2x4), warp tile 64x32.
// SMEM layout [row][k] stride 36 (conflict-free staging + fragment loads).
// mode 0: QKV scatter into g_Q/g_K/g_V. mode 1: row-major into Out.
// ===========================================================================
#define SROW 36
#define BUF_F (128 * SROW)                 // floats per (A or B) buffer
#define GEMM_SMEM (4 * BUF_F * 4)          // 2 bufs x (A+B) = 73728 bytes

__global__ void __launch_bounds__(256, 1)
gemm_mma(const float* __restrict__ A_in, const float* __restrict__ W,
         const float* __restrict__ bias, float* __restrict__ Out, int mode)
{
    extern __shared__ float sf[];
    const float* A = A_in ? A_in : g_ATT;
    const int K = C_;

    float* As = sf;                        // [2][128][36]
    float* Bs = sf + 2 * BUF_F;            // [2][128][36]

    int tid  = threadIdx.x;
    int lane = tid & 31;
    int warp = tid >> 5;
    int g    = lane >> 2;                  // 0..7
    int tig  = lane & 3;                   // 0..3
    int wm   = warp >> 2;                  // 0..1 -> m offset *64
    int wn   = warp & 3;                   // 0..3 -> n offset *32
    int bm   = blockIdx.y << 7;
    int bn   = blockIdx.x << 7;

    // Staging assignment: thread covers rows mrow+32s (s=0..3), 16B col chunk c4
    int mrow = tid >> 3;                   // 0..31
    int c4   = tid & 7;                    // 0..7 -> k cols 4*c4..4*c4+3
    const float* ga[4];
    const float* gb[4];
    int sts[4];
#pragma unroll
    for (int s = 0; s < 4; s++) {
        int m = mrow + (s << 5);
        ga[s]  = A + (size_t)(bm + m) * K + (c4 << 2);
        gb[s]  = W + (size_t)(bn + m) * K + (c4 << 2);
        sts[s] = m * SROW + (c4 << 2);
    }

    float acc[4][4][4];
#pragma unroll
    for (int i = 0; i < 4; i++)
#pragma unroll
        for (int j = 0; j < 4; j++)
#pragma unroll
            for (int r = 0; r < 4; r++) acc[i][j][r] = 0.f;

    // Prologue: stage chunk 0 into buffer 0
#pragma unroll
    for (int s = 0; s < 4; s++) {
        *(float4*)&As[sts[s]] = rnd4(*(const float4*)ga[s]);
        *(float4*)&Bs[sts[s]] = rnd4(*(const float4*)gb[s]);
    }
    __syncthreads();

    for (int kt = 0; kt < 64; kt++) {
        int buf = kt & 1;
        float4 pa[4], pb[4];
        if (kt < 63) {
#pragma unroll
            for (int s = 0; s < 4; s++) {
                pa[s] = *(const float4*)(ga[s] + (kt + 1) * 32);
                pb[s] = *(const float4*)(gb[s] + (kt + 1) * 32);
            }
        }

        const float* Ab = As + buf * BUF_F;
        const float* Bb = Bs + buf * BUF_F;

#pragma unroll
        for (int ks = 0; ks < 4; ks++) {
            int k0 = (ks << 3) + tig;
            uint32_t af[4][4], bf[4][2];
#pragma unroll
            for (int ma = 0; ma < 4; ma++) {
                int r = ((wm << 6) + (ma << 4) + g) * SROW + k0;
                af[ma][0] = __float_as_uint(Ab[r]);
                af[ma][1] = __float_as_uint(Ab[r + 8 * SROW]);
                af[ma][2] = __float_as_uint(Ab[r + 4]);
                af[ma][3] = __float_as_uint(Ab[r + 8 * SROW + 4]);
            }
#pragma unroll
            for (int na = 0; na < 4; na++) {
                int r = ((wn << 5) + (na << 3) + g) * SROW + k0;
                bf[na][0] = __float_as_uint(Bb[r]);
                bf[na][1] = __float_as_uint(Bb[r + 4]);
            }
#pragma unroll
            for (int ma = 0; ma < 4; ma++)
#pragma unroll
                for (int na = 0; na < 4; na++)
                    mma16n8k8(acc[ma][na], af[ma], bf[na]);
        }

        if (kt < 63) {
            int nbuf = 1 - buf;
            float* Aw = As + nbuf * BUF_F;
            float* Bw = Bs + nbuf * BUF_F;
#pragma unroll
            for (int s = 0; s < 4; s++) {
                *(float4*)&Aw[sts[s]] = rnd4(pa[s]);
                *(float4*)&Bw[sts[s]] = rnd4(pb[s]);
            }
            __syncthreads();
        }
    }

    // Epilogue: bias add + store (float2 per row-half per atom)
    int sel = blockIdx.x >> 4;             // mode 0: 0:q 1:k 2:v (BN=128 slice)
    int h   = blockIdx.x & 15;
    float* qkv_dst = (sel == 0) ? g_Q : ((sel == 1) ? g_K : g_V);

#pragma unroll
    for (int ma = 0; ma < 4; ma++) {
        int r0 = bm + (wm << 6) + (ma << 4) + g;
#pragma unroll
        for (int na = 0; na < 4; na++) {
            int cb = (wn << 5) + (na << 3) + (tig << 1);   // 0..127 within CTA
            int nglob = bn + cb;
            float b0 = bias[nglob];
            float b1 = bias[nglob + 1];
            float2 v0 = make_float2(acc[ma][na][0] + b0, acc[ma][na][1] + b1);
            float2 v1 = make_float2(acc[ma][na][2] + b0, acc[ma][na][3] + b1);
            if (mode == 0) {
                int bb0 = r0 >> 11, t0 = r0 & 2047;
                int r1 = r0 + 8;
                int bb1 = r1 >> 11, t1 = r1 & 2047;
                *(float2*)(qkv_dst + (((size_t)(bb0 * H_ + h)) * T_ + t0) * D_ + cb) = v0;
                *(float2*)(qkv_dst + (((size_t)(bb1 * H_ + h)) * T_ + t1) * D_ + cb) = v1;
            } else {
                *(float2*)(Out + (size_t)r0 * C_ + nglob)       = v0;
                *(float2*)(Out + (size_t)(r0 + 8) * C_ + nglob) = v1;
            }
        }
    }
}

// ---------------------------------------------------------------------------
// Flash attention (fp32, online softmax, causal block skipping) — unchanged
// from the Round-1 passing kernel.
// ---------------------------------------------------------------------------
#define QT_S 65
#define VS_S 132
#define PS_S 65
#define SMEM_ATTN ((2 * 128 * QT_S + 64 * VS_S + 64 * PS_S) * 4)

__global__ void __launch_bounds__(256)
attn_kernel()
{
    extern __shared__ float sm[];
    float* Qt = sm;
    float* Kt = Qt + 128 * QT_S;
    float* Vs = Kt + 128 * QT_S;
    float* Ps = Vs + 64 * VS_S;

    int tid = threadIdx.x;
    int tx = tid & 15;
    int ty = tid >> 4;
    int qb = blockIdx.x;
    int bh = blockIdx.y;

    const float* Qp = g_Q + (size_t)bh * T_ * D_ + (size_t)qb * 64 * D_;
    const float* Kp = g_K + (size_t)bh * T_ * D_;
    const float* Vp = g_V + (size_t)bh * T_ * D_;

#pragma unroll
    for (int s = 0; s < 8; s++) {
        int f = tid + (s << 8);
        int row = f >> 5;
        int dc = (f & 31) << 2;
        float4 v = *(const float4*)(Qp + (size_t)row * D_ + dc);
        Qt[(dc + 0) * QT_S + row] = v.x;
        Qt[(dc + 1) * QT_S + row] = v.y;
        Qt[(dc + 2) * QT_S + row] = v.z;
        Qt[(dc + 3) * QT_S + row] = v.w;
    }

    float m_i[4], l_i[4], o[4][8];
#pragma unroll
    for (int i = 0; i < 4; i++) {
        m_i[i] = -3.0e38f;
        l_i[i] = 0.f;
#pragma unroll
        for (int j = 0; j < 8; j++) o[i][j] = 0.f;
    }

    const float scale = 0.088388347648318447f;

    for (int kb = 0; kb <= qb; kb++) {
        __syncthreads();

#pragma unroll
        for (int s = 0; s < 8; s++) {
            int f = tid + (s << 8);
            int row = f >> 5;
            int dc = (f & 31) << 2;
            size_t goff = (size_t)(kb * 64 + row) * D_ + dc;
            float4 kv = *(const float4*)(Kp + goff);
            Kt[(dc + 0) * QT_S + row] = kv.x;
            Kt[(dc + 1) * QT_S + row] = kv.y;
            Kt[(dc + 2) * QT_S + row] = kv.z;
            Kt[(dc + 3) * QT_S + row] = kv.w;
            float4 vv = *(const float4*)(Vp + goff);
            *(float4*)(&Vs[row * VS_S + dc]) = vv;
        }
        __syncthreads();

        float sacc[4][4];
#pragma unroll
        for (int i = 0; i < 4; i++)
#pragma unroll
            for (int j = 0; j < 4; j++) sacc[i][j] = 0.f;

#pragma unroll 4
        for (int kk = 0; kk < 128; kk++) {
            float a[4], bv[4];
#pragma unroll
            for (int i = 0; i < 4; i++) a[i] = Qt[kk * QT_S + (ty << 2) + i];
#pragma unroll
            for (int j = 0; j < 4; j++) bv[j] = Kt[kk * QT_S + (tx << 2) + j];
#pragma unroll
            for (int i = 0; i < 4; i++)
#pragma unroll
                for (int j = 0; j < 4; j++)
                    sacc[i][j] = fmaf(a[i], bv[j], sacc[i][j]);
        }

        bool diag = (kb == qb);
        float p[4][4];
#pragma unroll
        for (int i = 0; i < 4; i++) {
            float rmax = -3.0e38f;
#pragma unroll
            for (int j = 0; j < 4; j++) {
                float sv = sacc[i][j] * scale;
                if (diag && ((tx << 2) + j) > ((ty << 2) + i)) sv = -3.0e38f;
                sacc[i][j] = sv;
                rmax = fmaxf(rmax, sv);
            }
#pragma unroll
            for (int off = 1; off < 16; off <<= 1)
                rmax = fmaxf(rmax, __shfl_xor_sync(0xffffffffu, rmax, off));
            float mnew = fmaxf(m_i[i], rmax);
            float alpha = __expf(m_i[i] - mnew);
            float rs = 0.f;
#pragma unroll
            for (int j = 0; j < 4; j++) {
                float pv = __expf(sacc[i][j] - mnew);
                p[i][j] = pv;
                rs += pv;
            }
#pragma unroll
            for (int off = 1; off < 16; off <<= 1)
                rs += __shfl_xor_sync(0xffffffffu, rs, off);
            l_i[i] = l_i[i] * alpha + rs;
            m_i[i] = mnew;
#pragma unroll
            for (int j = 0; j < 8; j++) o[i][j] *= alpha;
        }

#pragma unroll
        for (int i = 0; i < 4; i++)
#pragma unroll
            for (int j = 0; j < 4; j++)
                Ps[((ty << 2) + i) * PS_S + (tx << 2) + j] = p[i][j];
        __syncthreads();

#pragma unroll 4
        for (int kk = 0; kk < 64; kk++) {
            float a[4];
#pragma unroll
            for (int i = 0; i < 4; i++) a[i] = Ps[((ty << 2) + i) * PS_S + kk];
            float4 b0 = *(const float4*)(&Vs[kk * VS_S + (tx << 3)]);
            float4 b1 = *(const float4*)(&Vs[kk * VS_S + (tx << 3) + 4]);
            float bv[8] = {b0.x, b0.y, b0.z, b0.w, b1.x, b1.y, b1.z, b1.w};
#pragma unroll
            for (int i = 0; i < 4; i++)
#pragma unroll
                for (int j = 0; j < 8; j++)
                    o[i][j] = fmaf(a[i], bv[j], o[i][j]);
        }
    }

    int b = bh >> 4;
    int h = bh & 15;
#pragma unroll
    for (int i = 0; i < 4; i++) {
        int t = (qb << 6) + (ty << 2) + i;
        float inv = 1.f / l_i[i];
        size_t base = ((size_t)b * T_ + t) * C_ + (h << 7) + (tx << 3);
        float4 v0 = make_float4(o[i][0] * inv, o[i][1] * inv, o[i][2] * inv, o[i][3] * inv);
        float4 v1 = make_float4(o[i][4] * inv, o[i][5] * inv, o[i][6] * inv, o[i][7] * inv);
        *(float4*)(&g_ATT[base])     = v0;
        *(float4*)(&g_ATT[base + 4]) = v1;
    }
}

// ---------------------------------------------------------------------------
extern "C" void kernel_launch(void* const* d_in, const int* in_sizes, int n_in,
                              void* d_out, int out_size)
{
    const float* x      = (const float*)d_in[0];
    const float* qkv_w  = (const float*)d_in[1];
    const float* qkv_b  = (const float*)d_in[2];
    const float* proj_w = (const float*)d_in[3];
    const float* proj_b = (const float*)d_in[4];
    float* out = (float*)d_out;

    cudaFuncSetAttribute(gemm_mma, cudaFuncAttributeMaxDynamicSharedMemorySize,
                         GEMM_SMEM);
    cudaFuncSetAttribute(attn_kernel, cudaFuncAttributeMaxDynamicSharedMemorySize,
                         SMEM_ATTN);

    // 1) QKV projection (mma.sync tf32): [8192,2048] @ [6144,2048]^T + b
    gemm_mma<<<dim3(48, 64), 256, GEMM_SMEM>>>(x, qkv_w, qkv_b, nullptr, 0);

    // 2) causal flash attention -> g_ATT [B,T,C]
    attn_kernel<<<dim3(T_ / 64, B_ * H_), 256, SMEM_ATTN>>>();

    // 3) output projection (mma.sync tf32): g_ATT @ proj_w^T + proj_b -> out
    gemm_mma<<<dim3(16, 64), 256, GEMM_SMEM>>>(nullptr, proj_w, proj_b, out, 1);
}

// round 4
// speedup vs baseline: 3.7215x; 2.1130x over previous
#include <cuda_runtime.h>
#include <cstdint>

// Problem constants
#define B_ 4
#define T_ 2048
#define C_ 2048
#define H_ 16
#define D_ 128

// Scratch (device globals: allocation-free per harness rules)
__device__ float g_Q[(size_t)B_ * H_ * T_ * D_];     // [B,H,T,Dh]  (tf32-rounded)
__device__ float g_K[(size_t)B_ * H_ * T_ * D_];
__device__ float g_V[(size_t)B_ * H_ * T_ * D_];
__device__ float g_ATT[(size_t)B_ * T_ * C_];        // [B,T,C] (tf32-rounded)
__device__ float g_xr[(size_t)B_ * T_ * C_];         // rounded x
__device__ float g_wqkv[(size_t)3 * C_ * C_];        // rounded qkv_w
__device__ float g_wproj[(size_t)C_ * C_];           // rounded proj_w

// ---------------------------------------------------------------------------
// Helpers (sm_80-class PTX only — safe on base sm_103 target)
// ---------------------------------------------------------------------------
__device__ __forceinline__ uint32_t smem_u32(const void* p) {
    uint32_t a;
    asm("{ .reg .u64 t; cvta.to.shared.u64 t, %1; cvt.u32.u64 %0, t; }"
        : "=r"(a) : "l"(p));
    return a;
}
__device__ __forceinline__ void cpa16(uint32_t dst, const void* src) {
    asm volatile("cp.async.cg.shared.global [%0], [%1], 16;"
                 :: "r"(dst), "l"(src));
}
#define CP_COMMIT() asm volatile("cp.async.commit_group;" ::: "memory")
#define CP_WAIT(n)  asm volatile("cp.async.wait_group " #n ";" ::: "memory")

__device__ __forceinline__ float rnd_tf32(float x) {
    uint32_t u;
    asm("cvt.rna.tf32.f32 %0, %1;" : "=r"(u) : "f"(x));
    return __uint_as_float(u);
}
__device__ __forceinline__ float4 rnd4(float4 v) {
    v.x = rnd_tf32(v.x); v.y = rnd_tf32(v.y);
    v.z = rnd_tf32(v.z); v.w = rnd_tf32(v.w);
    return v;
}

// D(16x8,f32) += A(16x8,tf32) * B(8x8,tf32)
__device__ __forceinline__ void mma16n8k8(float c[4], const uint32_t a[4],
                                          const uint32_t b[2]) {
    asm volatile(
        "mma.sync.aligned.m16n8k8.row.col.f32.tf32.tf32.f32 "
        "{%0,%1,%2,%3}, {%4,%5,%6,%7}, {%8,%9}, {%0,%1,%2,%3};"
        : "+f"(c[0]), "+f"(c[1]), "+f"(c[2]), "+f"(c[3])
        : "r"(a[0]), "r"(a[1]), "r"(a[2]), "r"(a[3]), "r"(b[0]), "r"(b[1]));
}

// ---------------------------------------------------------------------------
// Prep: tf32-round copy (one pass per matrix)
// ---------------------------------------------------------------------------
__global__ void rnd_prep(const float4* __restrict__ src, int which, int n4)
{
    float4* dst = (which == 0) ? (float4*)g_xr
                : (which == 1) ? (float4*)g_wqkv : (float4*)g_wproj;
    int i = blockIdx.x * blockDim.x + threadIdx.x;
    if (i < n4) dst[i] = rnd4(src[i]);
}

// ===========================================================================
// tf32 GEMM: C[M,N] = A[M,2048] @ W[N,2048]^T + bias[N]
// CTA 256x128, 8 warps (4x2) at 64x64, BK=32, 3-stage cp.async pipeline.
// mode 0: A=g_xr, W=g_wqkv, scatter (rounded) into g_Q/g_K/g_V.
// mode 1: A=g_ATT, W=g_wproj, row-major fp32 into Out.
// ===========================================================================
#define GSROW 36
#define GA_STG (256 * GSROW)            // 9216 floats
#define GB_STG (128 * GSROW)            // 4608 floats
#define GEMM_SMEM (3 * (GA_STG + GB_STG) * 4)   // 165888 bytes

__global__ void __launch_bounds__(256, 1)
gemm_mma(const float* __restrict__ bias, float* __restrict__ Out, int mode)
{
    extern __shared__ float sf[];
    const float* A = (mode == 0) ? g_xr : g_ATT;
    const float* W = (mode == 0) ? g_wqkv : g_wproj;
    const int K = C_;

    uint32_t sbase = smem_u32(sf);
    uint32_t a_sm = sbase;
    uint32_t b_sm = sbase + 3 * GA_STG * 4;

    int tid  = threadIdx.x;
    int lane = tid & 31;
    int warp = tid >> 5;
    int g    = lane >> 2;
    int tig  = lane & 3;
    int wm   = warp >> 1;                // 0..3  (64 rows each)
    int wn   = warp & 1;                 // 0..1  (64 cols each)
    int bm   = blockIdx.y << 8;
    int bn   = blockIdx.x << 7;

    // cp.async source/dest bases: chunk id = tid + 256*s
    int crow = tid >> 3;                 // 0..31
    int cc4  = tid & 7;                  // 0..7
    const char* a_src0 = (const char*)(A + (size_t)(bm + crow) * K + (cc4 << 2));
    const char* b_src0 = (const char*)(W + (size_t)(bn + crow) * K + (cc4 << 2));
    uint32_t a_dst0 = (uint32_t)((crow * GSROW + (cc4 << 2)) * 4);
    uint32_t b_dst0 = (uint32_t)((crow * GSROW + (cc4 << 2)) * 4);

    float acc[4][8][4];
#pragma unroll
    for (int i = 0; i < 4; i++)
#pragma unroll
        for (int j = 0; j < 8; j++)
#pragma unroll
            for (int r = 0; r < 4; r++) acc[i][j][r] = 0.f;

    // ---- pipeline prologue: stages 0,1 ----
#pragma unroll
    for (int st = 0; st < 2; st++) {
        const char* asrc = a_src0 + (size_t)st * 128;   // 32 floats per kt
        const char* bsrc = b_src0 + (size_t)st * 128;
        uint32_t ad = a_sm + st * GA_STG * 4 + a_dst0;
        uint32_t bd = b_sm + st * GB_STG * 4 + b_dst0;
#pragma unroll
        for (int s = 0; s < 8; s++)
            cpa16(ad + s * (32 * GSROW * 4), asrc + (size_t)s * 32 * K * 4);
#pragma unroll
        for (int s = 0; s < 4; s++)
            cpa16(bd + s * (32 * GSROW * 4), bsrc + (size_t)s * 32 * K * 4);
        CP_COMMIT();
    }

    const int NKT = 64;
    for (int kt = 0; kt < NKT; kt++) {
        if (kt < NKT - 2) { CP_WAIT(1); } else { CP_WAIT(0); }
        __syncthreads();

        if (kt + 2 < NKT) {
            int st = kt + 2;
            int buf = st - (st / 3) * 3;
            const char* asrc = a_src0 + (size_t)st * 128;
            const char* bsrc = b_src0 + (size_t)st * 128;
            uint32_t ad = a_sm + buf * GA_STG * 4 + a_dst0;
            uint32_t bd = b_sm + buf * GB_STG * 4 + b_dst0;
#pragma unroll
            for (int s = 0; s < 8; s++)
                cpa16(ad + s * (32 * GSROW * 4), asrc + (size_t)s * 32 * K * 4);
#pragma unroll
            for (int s = 0; s < 4; s++)
                cpa16(bd + s * (32 * GSROW * 4), bsrc + (size_t)s * 32 * K * 4);
            CP_COMMIT();
        }

        int buf = kt - (kt / 3) * 3;
        const float* Ab = sf + buf * GA_STG;
        const float* Bb = sf + 3 * GA_STG + buf * GB_STG;

#pragma unroll
        for (int ks = 0; ks < 4; ks++) {
            int k0 = (ks << 3) + tig;
            uint32_t af[4][4], bf[8][2];
#pragma unroll
            for (int ma = 0; ma < 4; ma++) {
                int r = ((wm << 6) + (ma << 4) + g) * GSROW + k0;
                af[ma][0] = __float_as_uint(Ab[r]);
                af[ma][1] = __float_as_uint(Ab[r + 8 * GSROW]);
                af[ma][2] = __float_as_uint(Ab[r + 4]);
                af[ma][3] = __float_as_uint(Ab[r + 8 * GSROW + 4]);
            }
#pragma unroll
            for (int na = 0; na < 8; na++) {
                int r = ((wn << 6) + (na << 3) + g) * GSROW + k0;
                bf[na][0] = __float_as_uint(Bb[r]);
                bf[na][1] = __float_as_uint(Bb[r + 4]);
            }
#pragma unroll
            for (int ma = 0; ma < 4; ma++)
#pragma unroll
                for (int na = 0; na < 8; na++)
                    mma16n8k8(acc[ma][na], af[ma], bf[na]);
        }
    }

    // ---- epilogue ----
    int sel = blockIdx.x >> 4;           // mode 0 decode (N-tile = one slice)
    int hh  = blockIdx.x & 15;
    float* qkv_dst = (sel == 0) ? g_Q : ((sel == 1) ? g_K : g_V);

#pragma unroll
    for (int ma = 0; ma < 4; ma++) {
        int r0 = bm + (wm << 6) + (ma << 4) + g;
#pragma unroll
        for (int na = 0; na < 8; na++) {
            int cb = (wn << 6) + (na << 3) + (tig << 1);
            int nglob = bn + cb;
            float b0 = __ldg(bias + nglob);
            float b1 = __ldg(bias + nglob + 1);
            if (mode == 0) {
                float2 v0 = make_float2(rnd_tf32(acc[ma][na][0] + b0),
                                        rnd_tf32(acc[ma][na][1] + b1));
                float2 v1 = make_float2(rnd_tf32(acc[ma][na][2] + b0),
                                        rnd_tf32(acc[ma][na][3] + b1));
                int bb0 = r0 >> 11, t0 = r0 & 2047;
                int r1 = r0 + 8;
                int bb1 = r1 >> 11, t1 = r1 & 2047;
                *(float2*)(qkv_dst + (((size_t)(bb0 * H_ + hh)) * T_ + t0) * D_ + cb) = v0;
                *(float2*)(qkv_dst + (((size_t)(bb1 * H_ + hh)) * T_ + t1) * D_ + cb) = v1;
            } else {
                float2 v0 = make_float2(acc[ma][na][0] + b0, acc[ma][na][1] + b1);
                float2 v1 = make_float2(acc[ma][na][2] + b0, acc[ma][na][3] + b1);
                *(float2*)(Out + (size_t)r0 * C_ + nglob)       = v0;
                *(float2*)(Out + (size_t)(r0 + 8) * C_ + nglob) = v1;
            }
        }
    }
}

// ===========================================================================
// Flash attention on mma.sync tf32.
// CTA: 128 queries, 8 warps, KB=128 keys per iteration.
// S phase: warps (2q x 4key), 64x32 each. PV: warps (2q x 4d), 64x32 each.
// P is tf32-rounded and staged over the K buffer. O stays in registers.
// ===========================================================================
#define AROW 132
#define ATT_SMEM ((3 * 128 * AROW + 2 * 4 * 128) * 4)   // 206848 bytes

__global__ void __launch_bounds__(256, 1)
attn_mma()
{
    extern __shared__ float sf[];
    float* Qs   = sf;                        // [128][132]
    float* Ks   = sf + 128 * AROW;           // [128][132]  (aliased by P)
    float* Vs   = sf + 2 * 128 * AROW;       // [128][132]
    float* redm = sf + 3 * 128 * AROW;       // [4][128]
    float* reds = redm + 4 * 128;            // [4][128]

    uint32_t sbase = smem_u32(sf);
    uint32_t q_sm = sbase;
    uint32_t k_sm = sbase + 128 * AROW * 4;
    uint32_t v_sm = sbase + 2 * 128 * AROW * 4;

    int tid  = threadIdx.x;
    int lane = tid & 31;
    int warp = tid >> 5;
    int g    = lane >> 2;
    int tig  = lane & 3;
    int wm2  = warp >> 2;                    // 0..1 : q rows [wm2*64, +64)
    int wq   = warp & 3;                     // 0..3 : key stripe (S) / d stripe (PV)

    int qb = (int)gridDim.x - 1 - (int)blockIdx.x;   // heavy blocks first
    int bh = blockIdx.y;
    size_t bhoff = (size_t)bh * T_ * D_;

    // cp.async chunk assignment: id = tid + 256*s -> row=(id>>5), c4=(id&31)
    int crow = tid >> 5;                     // 0..7
    int cc4  = tid & 31;                     // 0..31
    uint32_t dst_off = (uint32_t)((crow * AROW + (cc4 << 2)) * 4);
    size_t   src_off = (size_t)crow * D_ + (cc4 << 2);

    // Q tile (once)
    {
        const float* qsrc = g_Q + bhoff + (size_t)qb * 128 * D_ + src_off;
#pragma unroll
        for (int s = 0; s < 16; s++)
            cpa16(q_sm + dst_off + s * (8 * AROW * 4), qsrc + (size_t)s * 8 * D_);
        CP_COMMIT();
    }

    float oacc[4][4][4];
#pragma unroll
    for (int i = 0; i < 4; i++)
#pragma unroll
        for (int j = 0; j < 4; j++)
#pragma unroll
            for (int r = 0; r < 4; r++) oacc[i][j][r] = 0.f;
    float m_i[8], l_i[8];
#pragma unroll
    for (int r = 0; r < 8; r++) { m_i[r] = -1.0e30f; l_i[r] = 0.f; }

    const float scale = 0.088388347648318447f;   // 1/sqrt(128)

    for (int kb = 0; kb <= qb; kb++) {
        __syncthreads();   // prior PV done with P(=Ks) and Vs
        {
            const float* ksrc = g_K + bhoff + (size_t)kb * 128 * D_ + src_off;
            const float* vsrc = g_V + bhoff + (size_t)kb * 128 * D_ + src_off;
#pragma unroll
            for (int s = 0; s < 16; s++)
                cpa16(k_sm + dst_off + s * (8 * AROW * 4), ksrc + (size_t)s * 8 * D_);
#pragma unroll
            for (int s = 0; s < 16; s++)
                cpa16(v_sm + dst_off + s * (8 * AROW * 4), vsrc + (size_t)s * 8 * D_);
            CP_COMMIT();
        }
        CP_WAIT(0);
        __syncthreads();

        // ---- S = Q K^T over this warp's 64x32 stripe ----
        float sacc[4][4][4];
#pragma unroll
        for (int i = 0; i < 4; i++)
#pragma unroll
            for (int j = 0; j < 4; j++)
#pragma unroll
                for (int r = 0; r < 4; r++) sacc[i][j][r] = 0.f;

#pragma unroll
        for (int ks = 0; ks < 16; ks++) {
            int k0 = (ks << 3) + tig;
            uint32_t af[4][4], bf[4][2];
#pragma unroll
            for (int ma = 0; ma < 4; ma++) {
                int r = ((wm2 << 6) + (ma << 4) + g) * AROW + k0;
                af[ma][0] = __float_as_uint(Qs[r]);
                af[ma][1] = __float_as_uint(Qs[r + 8 * AROW]);
                af[ma][2] = __float_as_uint(Qs[r + 4]);
                af[ma][3] = __float_as_uint(Qs[r + 8 * AROW + 4]);
            }
#pragma unroll
            for (int na = 0; na < 4; na++) {
                int r = ((wq << 5) + (na << 3) + g) * AROW + k0;
                bf[na][0] = __float_as_uint(Ks[r]);
                bf[na][1] = __float_as_uint(Ks[r + 4]);
            }
#pragma unroll
            for (int ma = 0; ma < 4; ma++)
#pragma unroll
                for (int na = 0; na < 4; na++)
                    mma16n8k8(sacc[ma][na], af[ma], bf[na]);
        }

        // ---- softmax: scale, mask, warp-stripe row max ----
        bool diag = (kb == qb);
        float rmax[8];
#pragma unroll
        for (int r = 0; r < 8; r++) rmax[r] = -1.0e30f;
#pragma unroll
        for (int ma = 0; ma < 4; ma++)
#pragma unroll
            for (int h = 0; h < 2; h++) {
                int row_l = (wm2 << 6) + (ma << 4) + g + (h << 3);
                int ri = (ma << 1) + h;
#pragma unroll
                for (int na = 0; na < 4; na++)
#pragma unroll
                    for (int e = 0; e < 2; e++) {
                        int col_l = (wq << 5) + (na << 3) + (tig << 1) + e;
                        float s = sacc[ma][na][(h << 1) + e] * scale;
                        if (diag && col_l > row_l) s = -1.0e30f;
                        sacc[ma][na][(h << 1) + e] = s;
                        rmax[ri] = fmaxf(rmax[ri], s);
                    }
            }
#pragma unroll
        for (int r = 0; r < 8; r++) {
            rmax[r] = fmaxf(rmax[r], __shfl_xor_sync(0xffffffffu, rmax[r], 1));
            rmax[r] = fmaxf(rmax[r], __shfl_xor_sync(0xffffffffu, rmax[r], 2));
        }
        if (tig == 0) {
#pragma unroll
            for (int ma = 0; ma < 4; ma++)
#pragma unroll
                for (int h = 0; h < 2; h++)
                    redm[(wq << 7) + (wm2 << 6) + (ma << 4) + g + (h << 3)] =
                        rmax[(ma << 1) + h];
        }
        __syncthreads();

        // global row max/alpha; p = exp(s - m); rounded-P sums; stage P over Ks
        float alpha[8], mnew[8], rsum[8];
#pragma unroll
        for (int ma = 0; ma < 4; ma++)
#pragma unroll
            for (int h = 0; h < 2; h++) {
                int row_l = (wm2 << 6) + (ma << 4) + g + (h << 3);
                int ri = (ma << 1) + h;
                float m4 = fmaxf(fmaxf(redm[row_l], redm[128 + row_l]),
                                 fmaxf(redm[256 + row_l], redm[384 + row_l]));
                mnew[ri] = fmaxf(m_i[ri], m4);
                alpha[ri] = __expf(m_i[ri] - mnew[ri]);
                m_i[ri] = mnew[ri];
                rsum[ri] = 0.f;
            }
#pragma unroll
        for (int ma = 0; ma < 4; ma++)
#pragma unroll
            for (int h = 0; h < 2; h++) {
                int ri = (ma << 1) + h;
                int row_l = (wm2 << 6) + (ma << 4) + g + (h << 3);
                float* prow = Ks + row_l * AROW + (wq << 5);
#pragma unroll
                for (int na = 0; na < 4; na++) {
                    float p0 = rnd_tf32(__expf(sacc[ma][na][(h << 1) + 0] - mnew[ri]));
                    float p1 = rnd_tf32(__expf(sacc[ma][na][(h << 1) + 1] - mnew[ri]));
                    rsum[ri] += p0 + p1;
                    *(float2*)(prow + (na << 3) + (tig << 1)) = make_float2(p0, p1);
                }
            }
#pragma unroll
        for (int r = 0; r < 8; r++) {
            rsum[r] += __shfl_xor_sync(0xffffffffu, rsum[r], 1);
            rsum[r] += __shfl_xor_sync(0xffffffffu, rsum[r], 2);
        }
        if (tig == 0) {
#pragma unroll
            for (int ma = 0; ma < 4; ma++)
#pragma unroll
                for (int h = 0; h < 2; h++)
                    reds[(wq << 7) + (wm2 << 6) + (ma << 4) + g + (h << 3)] =
                        rsum[(ma << 1) + h];
        }
        __syncthreads();

#pragma unroll
        for (int ma = 0; ma < 4; ma++)
#pragma unroll
            for (int h = 0; h < 2; h++) {
                int row_l = (wm2 << 6) + (ma << 4) + g + (h << 3);
                int ri = (ma << 1) + h;
                float ls = reds[row_l] + reds[128 + row_l] +
                           reds[256 + row_l] + reds[384 + row_l];
                l_i[ri] = l_i[ri] * alpha[ri] + ls;
            }
        // rescale O
#pragma unroll
        for (int ma = 0; ma < 4; ma++)
#pragma unroll
            for (int na = 0; na < 4; na++) {
                oacc[ma][na][0] *= alpha[(ma << 1)];
                oacc[ma][na][1] *= alpha[(ma << 1)];
                oacc[ma][na][2] *= alpha[(ma << 1) + 1];
                oacc[ma][na][3] *= alpha[(ma << 1) + 1];
            }

        // ---- O += P V : warp covers 64q x 32d, K=128 keys ----
#pragma unroll
        for (int ks = 0; ks < 16; ks++) {
            int k0 = (ks << 3) + tig;
            uint32_t af[4][4], bf[4][2];
#pragma unroll
            for (int ma = 0; ma < 4; ma++) {
                int r = ((wm2 << 6) + (ma << 4) + g) * AROW + k0;
                af[ma][0] = __float_as_uint(Ks[r]);
                af[ma][1] = __float_as_uint(Ks[r + 8 * AROW]);
                af[ma][2] = __float_as_uint(Ks[r + 4]);
                af[ma][3] = __float_as_uint(Ks[r + 8 * AROW + 4]);
            }
#pragma unroll
            for (int na = 0; na < 4; na++) {
                int d = (wq << 5) + (na << 3) + g;
                bf[na][0] = __float_as_uint(Vs[k0 * AROW + d]);
                bf[na][1] = __float_as_uint(Vs[(k0 + 4) * AROW + d]);
            }
#pragma unroll
            for (int ma = 0; ma < 4; ma++)
#pragma unroll
                for (int na = 0; na < 4; na++)
                    mma16n8k8(oacc[ma][na], af[ma], bf[na]);
        }
    }

    // ---- epilogue: normalize, round, write g_ATT [B,T,C] ----
    int b  = bh >> 4;
    int hh = bh & 15;
#pragma unroll
    for (int ma = 0; ma < 4; ma++)
#pragma unroll
        for (int h = 0; h < 2; h++) {
            int row_l = (wm2 << 6) + (ma << 4) + g + (h << 3);
            int ri = (ma << 1) + h;
            int t = (qb << 7) + row_l;
            float inv = 1.f / l_i[ri];
            size_t base = ((size_t)b * T_ + t) * C_ + (hh << 7);
#pragma unroll
            for (int na = 0; na < 4; na++) {
                int d0 = (wq << 5) + (na << 3) + (tig << 1);
                float2 v = make_float2(
                    rnd_tf32(oacc[ma][na][(h << 1) + 0] * inv),
                    rnd_tf32(oacc[ma][na][(h << 1) + 1] * inv));
                *(float2*)(g_ATT + base + d0) = v;
            }
        }
}

// ---------------------------------------------------------------------------
extern "C" void kernel_launch(void* const* d_in, const int* in_sizes, int n_in,
                              void* d_out, int out_size)
{
    const float* x      = (const float*)d_in[0];
    const float* qkv_w  = (const float*)d_in[1];
    const float* qkv_b  = (const float*)d_in[2];
    const float* proj_w = (const float*)d_in[3];
    const float* proj_b = (const float*)d_in[4];
    float* out = (float*)d_out;

    cudaFuncSetAttribute(gemm_mma, cudaFuncAttributeMaxDynamicSharedMemorySize,
                         GEMM_SMEM);
    cudaFuncSetAttribute(attn_mma, cudaFuncAttributeMaxDynamicSharedMemorySize,
                         ATT_SMEM);

    // 0) tf32 pre-round of GEMM inputs
    rnd_prep<<<(B_ * T_ * C_ / 4 + 255) / 256, 256>>>((const float4*)x, 0,
                                                      B_ * T_ * C_ / 4);
    rnd_prep<<<(3 * C_ * C_ / 4 + 255) / 256, 256>>>((const float4*)qkv_w, 1,
                                                     3 * C_ * C_ / 4);
    rnd_prep<<<(C_ * C_ / 4 + 255) / 256, 256>>>((const float4*)proj_w, 2,
                                                 C_ * C_ / 4);

    // 1) QKV projection: [8192,2048] @ [6144,2048]^T + b -> g_Q/g_K/g_V
    gemm_mma<<<dim3(48, 32), 256, GEMM_SMEM>>>(qkv_b, nullptr, 0);

    // 2) causal flash attention (tf32 mma) -> g_ATT [B,T,C]
    attn_mma<<<dim3(T_ / 128, B_ * H_), 256, ATT_SMEM>>>();

    // 3) output projection: g_ATT @ proj_w^T + proj_b -> out
    gemm_mma<<<dim3(16, 32), 256, GEMM_SMEM>>>(proj_b, out, 1);
}